// round 8
// baseline (speedup 1.0000x reference)
#include <cuda_runtime.h>
#include <cuda_bf16.h>
#include <cstdint>

// Problem constants
#define BATCH   2
#define SEQ     2048
#define DMODEL  1024
#define NHEADS  16
#define HDIM    64
#define TOKENS  (BATCH * SEQ)          // 4096
#define QKVDIM  (3 * DMODEL)           // 3072

// ---------------------------------------------------------------------------
// Scratch (no cudaMalloc allowed)
// ---------------------------------------------------------------------------
__device__ __nv_bfloat16 g_x_hi[(size_t)TOKENS * DMODEL];
__device__ __nv_bfloat16 g_x_lo[(size_t)TOKENS * DMODEL];
__device__ __nv_bfloat16 g_wqkv_hi[(size_t)QKVDIM * DMODEL];
__device__ __nv_bfloat16 g_wqkv_lo[(size_t)QKVDIM * DMODEL];
__device__ __nv_bfloat16 g_wout_hi[(size_t)DMODEL * DMODEL];
__device__ __nv_bfloat16 g_wout_lo[(size_t)DMODEL * DMODEL];
// head-major Q/K/V split: [which(3)][B*H][S][64]
__device__ __nv_bfloat16 g_hd_hi[(size_t)3 * TOKENS * DMODEL];
__device__ __nv_bfloat16 g_hd_lo[(size_t)3 * TOKENS * DMODEL];
// attention output, token-major [T][D], split
__device__ __nv_bfloat16 g_attn_hi[(size_t)TOKENS * DMODEL];
__device__ __nv_bfloat16 g_attn_lo[(size_t)TOKENS * DMODEL];

// ---------------------------------------------------------------------------
// Helpers (base ISA only — ptxas target is sm_103 without 'a')
// ---------------------------------------------------------------------------
__device__ __forceinline__ uint32_t smem_to_u32(const void* p) {
    uint32_t a;
    asm("{ .reg .u64 t; cvta.to.shared.u64 t, %1; cvt.u32.u64 %0, t; }" : "=r"(a) : "l"(p));
    return a;
}

#define CP_ASYNC16(dst, src) \
    asm volatile("cp.async.cg.shared.global [%0], [%1], 16;" :: "r"(dst), "l"(src) : "memory")
#define CP_COMMIT() asm volatile("cp.async.commit_group;" ::: "memory")
#define CP_WAIT(n)  asm volatile("cp.async.wait_group %0;" :: "n"(n) : "memory")

__device__ __forceinline__ void ldsm_x4(uint32_t addr, uint32_t& r0, uint32_t& r1,
                                        uint32_t& r2, uint32_t& r3) {
    asm volatile("ldmatrix.sync.aligned.m8n8.x4.shared.b16 {%0,%1,%2,%3}, [%4];"
                 : "=r"(r0), "=r"(r1), "=r"(r2), "=r"(r3) : "r"(addr));
}
__device__ __forceinline__ void ldsm_x4_t(uint32_t addr, uint32_t& r0, uint32_t& r1,
                                          uint32_t& r2, uint32_t& r3) {
    asm volatile("ldmatrix.sync.aligned.m8n8.x4.trans.shared.b16 {%0,%1,%2,%3}, [%4];"
                 : "=r"(r0), "=r"(r1), "=r"(r2), "=r"(r3) : "r"(addr));
}

__device__ __forceinline__ void mma_bf16(float* d, const uint32_t* a, const uint32_t* b) {
    asm volatile(
        "mma.sync.aligned.m16n8k16.row.col.f32.bf16.bf16.f32 "
        "{%0,%1,%2,%3}, {%4,%5,%6,%7}, {%8,%9}, {%0,%1,%2,%3};"
        : "+f"(d[0]), "+f"(d[1]), "+f"(d[2]), "+f"(d[3])
        : "r"(a[0]), "r"(a[1]), "r"(a[2]), "r"(a[3]), "r"(b[0]), "r"(b[1]));
}

__device__ __forceinline__ uint32_t pack_hi_bf16x2(float x, float y) {
    __nv_bfloat162 h = __floats2bfloat162_rn(x, y);
    return *(uint32_t*)&h;
}

// XOR swizzle for 64-byte rows (4 granules of 16B): conflict-free ldmatrix.
__device__ __forceinline__ uint32_t swz64(int row, int g) {
    return (uint32_t)(row * 64 + ((g ^ ((row >> 1) & 3)) << 4));
}

// ---------------------------------------------------------------------------
// Unified split kernel: fp32 -> (hi bf16, lo bf16) for x, w_qkv, w_out
// ---------------------------------------------------------------------------
#define NX4 (TOKENS * DMODEL / 4)     // 1048576
#define NQ4 (QKVDIM * DMODEL / 4)     // 786432
#define NO4 (DMODEL * DMODEL / 4)     // 262144

__global__ void __launch_bounds__(256)
split_all_kernel(const float* __restrict__ x, const float* __restrict__ wq,
                 const float* __restrict__ wo,
                 __nv_bfloat16* __restrict__ xh, __nv_bfloat16* __restrict__ xl,
                 __nv_bfloat16* __restrict__ wqh, __nv_bfloat16* __restrict__ wql,
                 __nv_bfloat16* __restrict__ woh, __nv_bfloat16* __restrict__ wol)
{
    int i = blockIdx.x * blockDim.x + threadIdx.x;
    const float* in; __nv_bfloat16 *hi, *lo; int j;
    if (i < NX4)              { in = x;  hi = xh;  lo = xl;  j = i; }
    else if (i < NX4 + NQ4)   { in = wq; hi = wqh; lo = wql; j = i - NX4; }
    else if (i < NX4 + NQ4 + NO4) { in = wo; hi = woh; lo = wol; j = i - NX4 - NQ4; }
    else return;

    float4 v = ((const float4*)in)[j];
    __nv_bfloat16 h0 = __float2bfloat16_rn(v.x);
    __nv_bfloat16 h1 = __float2bfloat16_rn(v.y);
    __nv_bfloat16 h2 = __float2bfloat16_rn(v.z);
    __nv_bfloat16 h3 = __float2bfloat16_rn(v.w);
    __nv_bfloat16 l0 = __float2bfloat16_rn(v.x - __bfloat162float(h0));
    __nv_bfloat16 l1 = __float2bfloat16_rn(v.y - __bfloat162float(h1));
    __nv_bfloat16 l2 = __float2bfloat16_rn(v.z - __bfloat162float(h2));
    __nv_bfloat16 l3 = __float2bfloat16_rn(v.w - __bfloat162float(h3));
    ((__nv_bfloat162*)hi)[2 * j]     = __nv_bfloat162(h0, h1);
    ((__nv_bfloat162*)hi)[2 * j + 1] = __nv_bfloat162(h2, h3);
    ((__nv_bfloat162*)lo)[2 * j]     = __nv_bfloat162(l0, l1);
    ((__nv_bfloat162*)lo)[2 * j + 1] = __nv_bfloat162(l2, l3);
}

// ---------------------------------------------------------------------------
// GEMM mainloop (128x128 tile, BK=32, 3 stages, swizzled 64B rows, 8 warps).
// ---------------------------------------------------------------------------
#define BK 32
#define NSTAGE 3
#define TILE_B (128 * 64)                  // 8192 bytes per 128x32 bf16 tile
#define STAGE_B (4 * TILE_B)               // 32768
#define GEMM_SMEM (NSTAGE * STAGE_B)       // 98304

__device__ __forceinline__ void gemm_load_stage(
    const __nv_bfloat16* __restrict__ Ahi, const __nv_bfloat16* __restrict__ Alo,
    const __nv_bfloat16* __restrict__ Bhi, const __nv_bfloat16* __restrict__ Blo,
    int K, int m0, int n0, int k0, uint32_t sbase, int tid)
{
#pragma unroll
    for (int t = 0; t < 8; t++) {
        int f    = tid + t * 256;
        int tile = f >> 9;
        int idx  = f & 511;
        int row  = idx >> 2;
        int g    = idx & 3;
        const __nv_bfloat16* src;
        if (tile == 0)      src = Ahi + (size_t)(m0 + row) * K + k0 + g * 8;
        else if (tile == 1) src = Alo + (size_t)(m0 + row) * K + k0 + g * 8;
        else if (tile == 2) src = Bhi + (size_t)(n0 + row) * K + k0 + g * 8;
        else                src = Blo + (size_t)(n0 + row) * K + k0 + g * 8;
        uint32_t dst = sbase + tile * TILE_B + swz64(row, g);
        CP_ASYNC16(dst, (const void*)src);
    }
}

// Mainloop: accumulates into acc[4][4][4]. One barrier per chunk.
#define GEMM_MAINLOOP(Ahi, Alo, Bhi, Blo, K) \
    float acc[4][4][4]; \
    _Pragma("unroll") for (int i = 0; i < 4; i++) \
    _Pragma("unroll") for (int j = 0; j < 4; j++) \
    _Pragma("unroll") for (int f = 0; f < 4; f++) acc[i][j][f] = 0.f; \
    gemm_load_stage(Ahi, Alo, Bhi, Blo, K, m0, n0, 0, smem_base, tid); \
    CP_COMMIT(); \
    gemm_load_stage(Ahi, Alo, Bhi, Blo, K, m0, n0, BK, smem_base + STAGE_B, tid); \
    CP_COMMIT(); \
    const int a_row_in_tile = wm * 64 + (lane & 15); \
    const int a_g           = lane >> 4; \
    const int b_row_in_tile = wn * 32 + ((lane >> 4) * 8) + (lane & 7); \
    const int b_g           = (lane >> 3) & 1; \
    const int nchunk = K / BK; \
    for (int i = 0; i < nchunk; i++) { \
        CP_WAIT(1); \
        __syncthreads(); \
        if (i + 2 < nchunk) \
            gemm_load_stage(Ahi, Alo, Bhi, Blo, K, m0, n0, (i + 2) * BK, \
                            smem_base + ((i + 2) % NSTAGE) * STAGE_B, tid); \
        CP_COMMIT(); \
        const uint32_t st = smem_base + (i % NSTAGE) * STAGE_B; \
        const uint32_t sAhi = st + 0 * TILE_B, sAlo = st + 1 * TILE_B; \
        const uint32_t sBhi = st + 2 * TILE_B, sBlo = st + 3 * TILE_B; \
        _Pragma("unroll") \
        for (int s = 0; s < 2; s++) { \
            uint32_t bh[4][2], bl[4][2]; \
            _Pragma("unroll") \
            for (int p = 0; p < 2; p++) { \
                uint32_t r0, r1, r2, r3; \
                ldsm_x4(sBhi + swz64(b_row_in_tile + p * 16, 2 * s + b_g), r0, r1, r2, r3); \
                bh[2 * p][0] = r0; bh[2 * p][1] = r1; bh[2 * p + 1][0] = r2; bh[2 * p + 1][1] = r3; \
                ldsm_x4(sBlo + swz64(b_row_in_tile + p * 16, 2 * s + b_g), r0, r1, r2, r3); \
                bl[2 * p][0] = r0; bl[2 * p][1] = r1; bl[2 * p + 1][0] = r2; bl[2 * p + 1][1] = r3; \
            } \
            _Pragma("unroll") \
            for (int mt = 0; mt < 4; mt++) { \
                uint32_t ah[4], al[4]; \
                ldsm_x4(sAhi + swz64(a_row_in_tile + mt * 16, 2 * s + a_g), \
                        ah[0], ah[1], ah[2], ah[3]); \
                ldsm_x4(sAlo + swz64(a_row_in_tile + mt * 16, 2 * s + a_g), \
                        al[0], al[1], al[2], al[3]); \
                _Pragma("unroll") \
                for (int nt = 0; nt < 4; nt++) { \
                    mma_bf16(acc[mt][nt], ah, bh[nt]); \
                    mma_bf16(acc[mt][nt], ah, bl[nt]); \
                    mma_bf16(acc[mt][nt], al, bh[nt]); \
                } \
            } \
        } \
    }

// ---------------------------------------------------------------------------
// QKV GEMM: writes head-major split q/k/v (Q pre-scaled by 1/8)
// ---------------------------------------------------------------------------
__global__ void __launch_bounds__(256, 2)
gemm_qkv(const __nv_bfloat16* __restrict__ Ahi, const __nv_bfloat16* __restrict__ Alo,
         const __nv_bfloat16* __restrict__ Bhi, const __nv_bfloat16* __restrict__ Blo,
         const float* __restrict__ bias,
         __nv_bfloat16* __restrict__ hd_hi, __nv_bfloat16* __restrict__ hd_lo)
{
    extern __shared__ __align__(128) unsigned char smem_raw[];
    const uint32_t smem_base = smem_to_u32(smem_raw);
    const int tid = threadIdx.x, wid = tid >> 5, lane = tid & 31;
    const int wm = wid >> 2, wn = wid & 3;
    const int m0 = blockIdx.y * 128, n0 = blockIdx.x * 128;
    const int K = DMODEL;

    GEMM_MAINLOOP(Ahi, Alo, Bhi, Blo, K)

    // Epilogue: scatter to head-major split arrays
    const int row_base = m0 + wm * 64 + (lane >> 2);
    const int col_base = n0 + wn * 32 + 2 * (lane & 3);
#pragma unroll
    for (int mt = 0; mt < 4; mt++) {
#pragma unroll
        for (int nt = 0; nt < 4; nt++) {
            int col = col_base + nt * 8;
            int which = col >> 10;
            int head  = (col >> 6) & 15;
            int dim   = col & 63;
            float b0 = bias[col], b1 = bias[col + 1];
            float sc = (which == 0) ? 0.125f : 1.0f;
#pragma unroll
            for (int rr = 0; rr < 2; rr++) {
                int row = row_base + mt * 16 + rr * 8;
                float v0 = (acc[mt][nt][2 * rr + 0] + b0) * sc;
                float v1 = (acc[mt][nt][2 * rr + 1] + b1) * sc;
                int bb = row >> 11, s = row & 2047;
                size_t addr = (((size_t)(which * (BATCH * NHEADS) + bb * NHEADS + head))
                               * SEQ + s) * HDIM + dim;
                uint32_t hp = pack_hi_bf16x2(v0, v1);
                __nv_bfloat162 hv = *(__nv_bfloat162*)&hp;
                float l0 = v0 - __bfloat162float(hv.x);
                float l1 = v1 - __bfloat162float(hv.y);
                *(uint32_t*)(hd_hi + addr) = hp;
                *(uint32_t*)(hd_lo + addr) = pack_hi_bf16x2(l0, l1);
            }
        }
    }
}

// ---------------------------------------------------------------------------
// Out-proj GEMM: fp32 output + bias
// ---------------------------------------------------------------------------
__global__ void __launch_bounds__(256, 2)
gemm_splitbf16(const __nv_bfloat16* __restrict__ Ahi, const __nv_bfloat16* __restrict__ Alo,
               const __nv_bfloat16* __restrict__ Bhi, const __nv_bfloat16* __restrict__ Blo,
               const float* __restrict__ bias, float* __restrict__ C,
               int M, int N, int K)
{
    extern __shared__ __align__(128) unsigned char smem_raw[];
    const uint32_t smem_base = smem_to_u32(smem_raw);
    const int tid = threadIdx.x, wid = tid >> 5, lane = tid & 31;
    const int wm = wid >> 2, wn = wid & 3;
    const int m0 = blockIdx.y * 128, n0 = blockIdx.x * 128;

    GEMM_MAINLOOP(Ahi, Alo, Bhi, Blo, K)

    const int row_base = m0 + wm * 64 + (lane >> 2);
    const int col_base = n0 + wn * 32 + 2 * (lane & 3);
#pragma unroll
    for (int mt = 0; mt < 4; mt++) {
#pragma unroll
        for (int nt = 0; nt < 4; nt++) {
            int col = col_base + nt * 8;
            float b0 = bias[col], b1 = bias[col + 1];
            int r0 = row_base + mt * 16;
            *(float2*)(C + (size_t)r0 * N + col) =
                make_float2(acc[mt][nt][0] + b0, acc[mt][nt][1] + b1);
            *(float2*)(C + (size_t)(r0 + 8) * N + col) =
                make_float2(acc[mt][nt][2] + b0, acc[mt][nt][3] + b1);
        }
    }
}

// ---------------------------------------------------------------------------
// Flash attention with mma.sync, split-bf16 precision.
// CTA: 128 q-rows x one (b,h). 8 warps, 16 rows each. KV chunks of 64.
// 2-stage KV pipeline, 2 CTAs/SM (register-dieted), two barriers per chunk.
// ---------------------------------------------------------------------------
#define AT_STRIDE_B 144                    // 72 bf16 per row
#define KV_TILE_B  (64 * AT_STRIDE_B)      // 9216
#define KV_STAGE_B (4 * KV_TILE_B)         // 36864
#define KV_NSTAGE  2
#define Q_TILE_B   (128 * AT_STRIDE_B)     // 18432
#define ATTN_SMEM  (2 * Q_TILE_B + KV_NSTAGE * KV_STAGE_B)   // 110592

__device__ __forceinline__ void attn_load_kv(
    const __nv_bfloat16* Kh, const __nv_bfloat16* Kl,
    const __nv_bfloat16* Vh, const __nv_bfloat16* Vl,
    int kc, uint32_t stg, int tid)
{
#pragma unroll
    for (int t = 0; t < 8; t++) {
        int f = tid + t * 256;
        int tile = f >> 9;
        int idx  = f & 511;
        int row  = idx >> 3;
        int g    = idx & 7;
        const __nv_bfloat16* src;
        if (tile == 0)      src = Kh + (size_t)(kc + row) * HDIM + g * 8;
        else if (tile == 1) src = Kl + (size_t)(kc + row) * HDIM + g * 8;
        else if (tile == 2) src = Vh + (size_t)(kc + row) * HDIM + g * 8;
        else                src = Vl + (size_t)(kc + row) * HDIM + g * 8;
        uint32_t dst = stg + tile * KV_TILE_B + row * AT_STRIDE_B + g * 16;
        CP_ASYNC16(dst, (const void*)src);
    }
}

__global__ void __launch_bounds__(256, 2)
attn_mma(const __nv_bfloat16* __restrict__ hd_hi, const __nv_bfloat16* __restrict__ hd_lo,
         __nv_bfloat16* __restrict__ out_hi, __nv_bfloat16* __restrict__ out_lo)
{
    extern __shared__ __align__(128) unsigned char smem_raw[];
    const uint32_t smem_base = smem_to_u32(smem_raw);
    const int tid  = threadIdx.x;
    const int w    = tid >> 5;
    const int lane = tid & 31;
    const int bh   = blockIdx.y;
    const int q0   = (gridDim.x - 1 - blockIdx.x) * 128;   // longest CTAs first
    const int b    = bh >> 4;
    const int h    = bh & 15;

    const size_t headelems = (size_t)SEQ * HDIM;
    const __nv_bfloat16* Qh = hd_hi + (size_t)bh * headelems;
    const __nv_bfloat16* Ql = hd_lo + (size_t)bh * headelems;
    const __nv_bfloat16* Kh = hd_hi + (size_t)(BATCH * NHEADS + bh) * headelems;
    const __nv_bfloat16* Kl = hd_lo + (size_t)(BATCH * NHEADS + bh) * headelems;
    const __nv_bfloat16* Vh = hd_hi + (size_t)(2 * BATCH * NHEADS + bh) * headelems;
    const __nv_bfloat16* Vl = hd_lo + (size_t)(2 * BATCH * NHEADS + bh) * headelems;

    const uint32_t sQh = smem_base;
    const uint32_t sQl = smem_base + Q_TILE_B;
    const uint32_t kvbase = smem_base + 2 * Q_TILE_B;

    // ---- Prologue: Q tile + KV chunk 0 (group 0), KV chunk 1 (group 1) ----
#pragma unroll
    for (int t = 0; t < 8; t++) {
        int f = tid + t * 256;           // 0..2047
        int half = f >> 10;
        int idx  = f & 1023;
        int row  = idx >> 3;
        int g    = idx & 7;
        const __nv_bfloat16* src = (half ? Ql : Qh) + (size_t)(q0 + row) * HDIM + g * 8;
        uint32_t dst = (half ? sQl : sQh) + row * AT_STRIDE_B + g * 16;
        CP_ASYNC16(dst, (const void*)src);
    }
    attn_load_kv(Kh, Kl, Vh, Vl, 0, kvbase, tid);
    CP_COMMIT();
    attn_load_kv(Kh, Kl, Vh, Vl, 64, kvbase + KV_STAGE_B, tid);
    CP_COMMIT();

    const int nch = q0 / 64 + 2;

    // per-thread state (register-dieted: Q-hi resident, Q-lo reloaded per chunk)
    uint32_t qh[4][4];
    float o[8][4];
#pragma unroll
    for (int j = 0; j < 8; j++)
#pragma unroll
        for (int e = 0; e < 4; e++) o[j][e] = 0.f;
    float m0r = -1e30f, m1r = -1e30f, l0r = 0.f, l1r = 0.f;
    bool qloaded = false;

    const int g0 = q0 + 16 * w + (lane >> 2);
    const int g1 = g0 + 8;
    const int cb = 2 * (lane & 3);
    const int krow  = ((lane >> 4) * 8) + (lane & 7);
    const int kcolb = ((lane >> 3) & 1) * 16;
    const uint32_t qrow_off = (16 * w + (lane & 15)) * AT_STRIDE_B + (lane >> 4) * 16;

    for (int c = 0; c < nch; c++) {
        CP_WAIT(1);
        __syncthreads();

        if (!qloaded) {
            qloaded = true;
#pragma unroll
            for (int s = 0; s < 4; s++)
                ldsm_x4(sQh + qrow_off + s * 32, qh[s][0], qh[s][1], qh[s][2], qh[s][3]);
        }

        const int kc = c * 64;
        const bool active = (kc <= q0 + 16 * w + 15);
        if (active) {
            const uint32_t stg = kvbase + (c & 1) * KV_STAGE_B;
            const uint32_t sKh = stg, sKl = stg + KV_TILE_B;
            const uint32_t sVh = stg + 2 * KV_TILE_B, sVl = stg + 3 * KV_TILE_B;

            // ---- S = Q K^T (3-pass split; Q-lo reloaded from smem) ----
            float sfr[8][4];
#pragma unroll
            for (int j = 0; j < 8; j++)
#pragma unroll
                for (int e = 0; e < 4; e++) sfr[j][e] = 0.f;

#pragma unroll
            for (int s = 0; s < 4; s++) {
                uint32_t qls[4];
                ldsm_x4(sQl + qrow_off + s * 32, qls[0], qls[1], qls[2], qls[3]);
#pragma unroll
                for (int p = 0; p < 4; p++) {
                    uint32_t h0, h1, h2, h3, lo0, lo1, lo2, lo3;
                    ldsm_x4(sKh + (16 * p + krow) * AT_STRIDE_B + s * 32 + kcolb, h0, h1, h2, h3);
                    ldsm_x4(sKl + (16 * p + krow) * AT_STRIDE_B + s * 32 + kcolb, lo0, lo1, lo2, lo3);
                    uint32_t bh0[2] = {h0, h1}, bh1[2] = {h2, h3};
                    uint32_t bl0[2] = {lo0, lo1}, bl1[2] = {lo2, lo3};
                    mma_bf16(sfr[2 * p],     qh[s], bh0);
                    mma_bf16(sfr[2 * p],     qh[s], bl0);
                    mma_bf16(sfr[2 * p],     qls,   bh0);
                    mma_bf16(sfr[2 * p + 1], qh[s], bh1);
                    mma_bf16(sfr[2 * p + 1], qh[s], bl1);
                    mma_bf16(sfr[2 * p + 1], qls,   bh1);
                }
            }

            // ---- causal mask ----
            if (kc + 63 > g0) {
#pragma unroll
                for (int j = 0; j < 8; j++) {
                    int col = kc + 8 * j + cb;
                    if (col     > g0) sfr[j][0] = -1e30f;
                    if (col + 1 > g0) sfr[j][1] = -1e30f;
                    if (col     > g1) sfr[j][2] = -1e30f;
                    if (col + 1 > g1) sfr[j][3] = -1e30f;
                }
            }

            // ---- online softmax (exp in place into sfr) ----
            float mx0 = -1e30f, mx1 = -1e30f;
#pragma unroll
            for (int j = 0; j < 8; j++) {
                mx0 = fmaxf(mx0, fmaxf(sfr[j][0], sfr[j][1]));
                mx1 = fmaxf(mx1, fmaxf(sfr[j][2], sfr[j][3]));
            }
            mx0 = fmaxf(mx0, __shfl_xor_sync(0xffffffffu, mx0, 1));
            mx0 = fmaxf(mx0, __shfl_xor_sync(0xffffffffu, mx0, 2));
            mx1 = fmaxf(mx1, __shfl_xor_sync(0xffffffffu, mx1, 1));
            mx1 = fmaxf(mx1, __shfl_xor_sync(0xffffffffu, mx1, 2));

            float mn0 = fmaxf(m0r, mx0), mn1 = fmaxf(m1r, mx1);
            float cr0 = __expf(m0r - mn0), cr1 = __expf(m1r - mn1);
            float sum0 = 0.f, sum1 = 0.f;
#pragma unroll
            for (int j = 0; j < 8; j++) {
                sfr[j][0] = __expf(sfr[j][0] - mn0);
                sfr[j][1] = __expf(sfr[j][1] - mn0);
                sfr[j][2] = __expf(sfr[j][2] - mn1);
                sfr[j][3] = __expf(sfr[j][3] - mn1);
                sum0 += sfr[j][0] + sfr[j][1];
                sum1 += sfr[j][2] + sfr[j][3];
            }
            sum0 += __shfl_xor_sync(0xffffffffu, sum0, 1);
            sum0 += __shfl_xor_sync(0xffffffffu, sum0, 2);
            sum1 += __shfl_xor_sync(0xffffffffu, sum1, 1);
            sum1 += __shfl_xor_sync(0xffffffffu, sum1, 2);

            l0r = l0r * cr0 + sum0;
            l1r = l1r * cr1 + sum1;
            m0r = mn0; m1r = mn1;
#pragma unroll
            for (int j = 0; j < 8; j++) {
                o[j][0] *= cr0; o[j][1] *= cr0;
                o[j][2] *= cr1; o[j][3] *= cr1;
            }

            // ---- O += P V (fused pack + 3-pass split) ----
#pragma unroll
            for (int t = 0; t < 4; t++) {
                uint32_t ph[4], pl[4];
                {
                    const float* s0p = sfr[2 * t];
                    const float* s1p = sfr[2 * t + 1];
                    float v[8] = {s0p[0], s0p[1], s0p[2], s0p[3],
                                  s1p[0], s1p[1], s1p[2], s1p[3]};
#pragma unroll
                    for (int q = 0; q < 4; q++) {
                        uint32_t hp = pack_hi_bf16x2(v[2 * q], v[2 * q + 1]);
                        __nv_bfloat162 hv = *(__nv_bfloat162*)&hp;
                        float lo0 = v[2 * q]     - __bfloat162float(hv.x);
                        float lo1 = v[2 * q + 1] - __bfloat162float(hv.y);
                        ph[q] = hp;
                        pl[q] = pack_hi_bf16x2(lo0, lo1);
                    }
                }
#pragma unroll
                for (int d = 0; d < 4; d++) {
                    uint32_t v0, v1, v2, v3, w0, w1, w2, w3;
                    uint32_t a = sVh + (16 * t + (lane & 15)) * AT_STRIDE_B + d * 32 + (lane >> 4) * 16;
                    ldsm_x4_t(a, v0, v1, v2, v3);
                    a = sVl + (16 * t + (lane & 15)) * AT_STRIDE_B + d * 32 + (lane >> 4) * 16;
                    ldsm_x4_t(a, w0, w1, w2, w3);
                    uint32_t bh0[2] = {v0, v1}, bh1[2] = {v2, v3};
                    uint32_t bl0[2] = {w0, w1}, bl1[2] = {w2, w3};
                    mma_bf16(o[2 * d],     ph, bh0);
                    mma_bf16(o[2 * d],     ph, bl0);
                    mma_bf16(o[2 * d],     pl, bh0);
                    mma_bf16(o[2 * d + 1], ph, bh1);
                    mma_bf16(o[2 * d + 1], ph, bl1);
                    mma_bf16(o[2 * d + 1], pl, bh1);
                }
            }
        }
        __syncthreads();   // all warps done reading stage c%2
        if (c + 2 < nch)
            attn_load_kv(Kh, Kl, Vh, Vl, (c + 2) * 64,
                         kvbase + (c & 1) * KV_STAGE_B, tid);
        CP_COMMIT();
    }

    // ---- epilogue: normalize, split, store ----
    const float i0 = 1.0f / l0r, i1 = 1.0f / l1r;
    const size_t base0 = ((size_t)(b * SEQ + g0)) * DMODEL + h * HDIM + cb;
    const size_t base1 = ((size_t)(b * SEQ + g1)) * DMODEL + h * HDIM + cb;
#pragma unroll
    for (int j = 0; j < 8; j++) {
        float x0 = o[j][0] * i0, x1 = o[j][1] * i0;
        float y0 = o[j][2] * i1, y1 = o[j][3] * i1;
        uint32_t hp0 = pack_hi_bf16x2(x0, x1);
        __nv_bfloat162 hv0 = *(__nv_bfloat162*)&hp0;
        uint32_t lp0 = pack_hi_bf16x2(x0 - __bfloat162float(hv0.x),
                                      x1 - __bfloat162float(hv0.y));
        uint32_t hp1 = pack_hi_bf16x2(y0, y1);
        __nv_bfloat162 hv1 = *(__nv_bfloat162*)&hp1;
        uint32_t lp1 = pack_hi_bf16x2(y0 - __bfloat162float(hv1.x),
                                      y1 - __bfloat162float(hv1.y));
        *(uint32_t*)(out_hi + base0 + 8 * j) = hp0;
        *(uint32_t*)(out_lo + base0 + 8 * j) = lp0;
        *(uint32_t*)(out_hi + base1 + 8 * j) = hp1;
        *(uint32_t*)(out_lo + base1 + 8 * j) = lp1;
    }
}

// ---------------------------------------------------------------------------
// Launch
// ---------------------------------------------------------------------------
extern "C" void kernel_launch(void* const* d_in, const int* in_sizes, int n_in,
                              void* d_out, int out_size)
{
    const float* x     = (const float*)d_in[0];
    const float* w_qkv = (const float*)d_in[1];
    const float* b_qkv = (const float*)d_in[2];
    const float* w_out = (const float*)d_in[3];
    const float* b_out = (const float*)d_in[4];
    float* out = (float*)d_out;

    __nv_bfloat16 *x_hi, *x_lo, *wq_hi, *wq_lo, *wo_hi, *wo_lo;
    __nv_bfloat16 *hd_hi, *hd_lo, *at_hi, *at_lo;
    cudaGetSymbolAddress((void**)&x_hi,  g_x_hi);
    cudaGetSymbolAddress((void**)&x_lo,  g_x_lo);
    cudaGetSymbolAddress((void**)&wq_hi, g_wqkv_hi);
    cudaGetSymbolAddress((void**)&wq_lo, g_wqkv_lo);
    cudaGetSymbolAddress((void**)&wo_hi, g_wout_hi);
    cudaGetSymbolAddress((void**)&wo_lo, g_wout_lo);
    cudaGetSymbolAddress((void**)&hd_hi, g_hd_hi);
    cudaGetSymbolAddress((void**)&hd_lo, g_hd_lo);
    cudaGetSymbolAddress((void**)&at_hi, g_attn_hi);
    cudaGetSymbolAddress((void**)&at_lo, g_attn_lo);

    cudaFuncSetAttribute(gemm_qkv,
                         cudaFuncAttributeMaxDynamicSharedMemorySize, GEMM_SMEM);
    cudaFuncSetAttribute(gemm_splitbf16,
                         cudaFuncAttributeMaxDynamicSharedMemorySize, GEMM_SMEM);
    cudaFuncSetAttribute(attn_mma,
                         cudaFuncAttributeMaxDynamicSharedMemorySize, ATTN_SMEM);

    // Unified splits (1 launch)
    {
        int total = NX4 + NQ4 + NO4;
        split_all_kernel<<<(total + 255) / 256, 256>>>(
            x, w_qkv, w_out, x_hi, x_lo, wq_hi, wq_lo, wo_hi, wo_lo);
    }

    // 1) QKV projection -> head-major split q/k/v
    {
        dim3 grid(QKVDIM / 128, TOKENS / 128);
        gemm_qkv<<<grid, 256, GEMM_SMEM>>>(x_hi, x_lo, wq_hi, wq_lo, b_qkv, hd_hi, hd_lo);
    }

    // 2) Flash attention (tensor cores, 2 CTAs/SM) -> split attn output
    {
        dim3 grid(SEQ / 128, BATCH * NHEADS);
        attn_mma<<<grid, 256, ATTN_SMEM>>>(hd_hi, hd_lo, at_hi, at_lo);
    }

    // 3) Output projection
    {
        dim3 grid(DMODEL / 128, TOKENS / 128);
        gemm_splitbf16<<<grid, 256, GEMM_SMEM>>>(
            at_hi, at_lo, wo_hi, wo_lo, b_out, out, TOKENS, DMODEL, DMODEL);
    }
}

// round 9
// speedup vs baseline: 1.0716x; 1.0716x over previous
#include <cuda_runtime.h>
#include <cuda_bf16.h>
#include <cstdint>

// Problem constants
#define BATCH   2
#define SEQ     2048
#define DMODEL  1024
#define NHEADS  16
#define HDIM    64
#define TOKENS  (BATCH * SEQ)          // 4096
#define QKVDIM  (3 * DMODEL)           // 3072

// ---------------------------------------------------------------------------
// Scratch (no cudaMalloc allowed)
// ---------------------------------------------------------------------------
__device__ __nv_bfloat16 g_x_hi[(size_t)TOKENS * DMODEL];
__device__ __nv_bfloat16 g_x_lo[(size_t)TOKENS * DMODEL];
__device__ __nv_bfloat16 g_wqkv_hi[(size_t)QKVDIM * DMODEL];
__device__ __nv_bfloat16 g_wqkv_lo[(size_t)QKVDIM * DMODEL];
__device__ __nv_bfloat16 g_wout_hi[(size_t)DMODEL * DMODEL];
__device__ __nv_bfloat16 g_wout_lo[(size_t)DMODEL * DMODEL];
// head-major Q/K/V split: [which(3)][B*H][S][64]
__device__ __nv_bfloat16 g_hd_hi[(size_t)3 * TOKENS * DMODEL];
__device__ __nv_bfloat16 g_hd_lo[(size_t)3 * TOKENS * DMODEL];
// attention output, token-major [T][D], split
__device__ __nv_bfloat16 g_attn_hi[(size_t)TOKENS * DMODEL];
__device__ __nv_bfloat16 g_attn_lo[(size_t)TOKENS * DMODEL];

// ---------------------------------------------------------------------------
// Helpers (base ISA only — ptxas target is sm_103 without 'a')
// ---------------------------------------------------------------------------
__device__ __forceinline__ uint32_t smem_to_u32(const void* p) {
    uint32_t a;
    asm("{ .reg .u64 t; cvta.to.shared.u64 t, %1; cvt.u32.u64 %0, t; }" : "=r"(a) : "l"(p));
    return a;
}

#define CP_ASYNC16(dst, src) \
    asm volatile("cp.async.cg.shared.global [%0], [%1], 16;" :: "r"(dst), "l"(src) : "memory")
#define CP_COMMIT() asm volatile("cp.async.commit_group;" ::: "memory")
#define CP_WAIT(n)  asm volatile("cp.async.wait_group %0;" :: "n"(n) : "memory")

__device__ __forceinline__ void ldsm_x4(uint32_t addr, uint32_t& r0, uint32_t& r1,
                                        uint32_t& r2, uint32_t& r3) {
    asm volatile("ldmatrix.sync.aligned.m8n8.x4.shared.b16 {%0,%1,%2,%3}, [%4];"
                 : "=r"(r0), "=r"(r1), "=r"(r2), "=r"(r3) : "r"(addr));
}
__device__ __forceinline__ void ldsm_x4_t(uint32_t addr, uint32_t& r0, uint32_t& r1,
                                          uint32_t& r2, uint32_t& r3) {
    asm volatile("ldmatrix.sync.aligned.m8n8.x4.trans.shared.b16 {%0,%1,%2,%3}, [%4];"
                 : "=r"(r0), "=r"(r1), "=r"(r2), "=r"(r3) : "r"(addr));
}

__device__ __forceinline__ void mma_bf16(float* d, const uint32_t* a, const uint32_t* b) {
    asm volatile(
        "mma.sync.aligned.m16n8k16.row.col.f32.bf16.bf16.f32 "
        "{%0,%1,%2,%3}, {%4,%5,%6,%7}, {%8,%9}, {%0,%1,%2,%3};"
        : "+f"(d[0]), "+f"(d[1]), "+f"(d[2]), "+f"(d[3])
        : "r"(a[0]), "r"(a[1]), "r"(a[2]), "r"(a[3]), "r"(b[0]), "r"(b[1]));
}

__device__ __forceinline__ uint32_t pack_hi_bf16x2(float x, float y) {
    __nv_bfloat162 h = __floats2bfloat162_rn(x, y);
    return *(uint32_t*)&h;
}

// XOR swizzle for 64-byte rows (4 granules of 16B): conflict-free ldmatrix.
__device__ __forceinline__ uint32_t swz64(int row, int g) {
    return (uint32_t)(row * 64 + ((g ^ ((row >> 1) & 3)) << 4));
}

// ---------------------------------------------------------------------------
// Unified split kernel: fp32 -> (hi bf16, lo bf16) for x, w_qkv, w_out
// ---------------------------------------------------------------------------
#define NX4 (TOKENS * DMODEL / 4)     // 1048576
#define NQ4 (QKVDIM * DMODEL / 4)     // 786432
#define NO4 (DMODEL * DMODEL / 4)     // 262144

__global__ void __launch_bounds__(256)
split_all_kernel(const float* __restrict__ x, const float* __restrict__ wq,
                 const float* __restrict__ wo,
                 __nv_bfloat16* __restrict__ xh, __nv_bfloat16* __restrict__ xl,
                 __nv_bfloat16* __restrict__ wqh, __nv_bfloat16* __restrict__ wql,
                 __nv_bfloat16* __restrict__ woh, __nv_bfloat16* __restrict__ wol)
{
    int i = blockIdx.x * blockDim.x + threadIdx.x;
    const float* in; __nv_bfloat16 *hi, *lo; int j;
    if (i < NX4)              { in = x;  hi = xh;  lo = xl;  j = i; }
    else if (i < NX4 + NQ4)   { in = wq; hi = wqh; lo = wql; j = i - NX4; }
    else if (i < NX4 + NQ4 + NO4) { in = wo; hi = woh; lo = wol; j = i - NX4 - NQ4; }
    else return;

    float4 v = ((const float4*)in)[j];
    __nv_bfloat16 h0 = __float2bfloat16_rn(v.x);
    __nv_bfloat16 h1 = __float2bfloat16_rn(v.y);
    __nv_bfloat16 h2 = __float2bfloat16_rn(v.z);
    __nv_bfloat16 h3 = __float2bfloat16_rn(v.w);
    __nv_bfloat16 l0 = __float2bfloat16_rn(v.x - __bfloat162float(h0));
    __nv_bfloat16 l1 = __float2bfloat16_rn(v.y - __bfloat162float(h1));
    __nv_bfloat16 l2 = __float2bfloat16_rn(v.z - __bfloat162float(h2));
    __nv_bfloat16 l3 = __float2bfloat16_rn(v.w - __bfloat162float(h3));
    ((__nv_bfloat162*)hi)[2 * j]     = __nv_bfloat162(h0, h1);
    ((__nv_bfloat162*)hi)[2 * j + 1] = __nv_bfloat162(h2, h3);
    ((__nv_bfloat162*)lo)[2 * j]     = __nv_bfloat162(l0, l1);
    ((__nv_bfloat162*)lo)[2 * j + 1] = __nv_bfloat162(l2, l3);
}

// ---------------------------------------------------------------------------
// GEMM mainloop (128x128 tile, BK=32, 3 stages, swizzled 64B rows, 8 warps).
// (R7 best-known configuration, unchanged.)
// ---------------------------------------------------------------------------
#define BK 32
#define NSTAGE 3
#define TILE_B (128 * 64)                  // 8192 bytes per 128x32 bf16 tile
#define STAGE_B (4 * TILE_B)               // 32768
#define GEMM_SMEM (NSTAGE * STAGE_B)       // 98304

__device__ __forceinline__ void gemm_load_stage(
    const __nv_bfloat16* __restrict__ Ahi, const __nv_bfloat16* __restrict__ Alo,
    const __nv_bfloat16* __restrict__ Bhi, const __nv_bfloat16* __restrict__ Blo,
    int K, int m0, int n0, int k0, uint32_t sbase, int tid)
{
#pragma unroll
    for (int t = 0; t < 8; t++) {
        int f    = tid + t * 256;
        int tile = f >> 9;
        int idx  = f & 511;
        int row  = idx >> 2;
        int g    = idx & 3;
        const __nv_bfloat16* src;
        if (tile == 0)      src = Ahi + (size_t)(m0 + row) * K + k0 + g * 8;
        else if (tile == 1) src = Alo + (size_t)(m0 + row) * K + k0 + g * 8;
        else if (tile == 2) src = Bhi + (size_t)(n0 + row) * K + k0 + g * 8;
        else                src = Blo + (size_t)(n0 + row) * K + k0 + g * 8;
        uint32_t dst = sbase + tile * TILE_B + swz64(row, g);
        CP_ASYNC16(dst, (const void*)src);
    }
}

#define GEMM_MAINLOOP(Ahi, Alo, Bhi, Blo, K) \
    float acc[4][4][4]; \
    _Pragma("unroll") for (int i = 0; i < 4; i++) \
    _Pragma("unroll") for (int j = 0; j < 4; j++) \
    _Pragma("unroll") for (int f = 0; f < 4; f++) acc[i][j][f] = 0.f; \
    gemm_load_stage(Ahi, Alo, Bhi, Blo, K, m0, n0, 0, smem_base, tid); \
    CP_COMMIT(); \
    gemm_load_stage(Ahi, Alo, Bhi, Blo, K, m0, n0, BK, smem_base + STAGE_B, tid); \
    CP_COMMIT(); \
    const int a_row_in_tile = wm * 64 + (lane & 15); \
    const int a_g           = lane >> 4; \
    const int b_row_in_tile = wn * 32 + ((lane >> 4) * 8) + (lane & 7); \
    const int b_g           = (lane >> 3) & 1; \
    const int nchunk = K / BK; \
    for (int i = 0; i < nchunk; i++) { \
        CP_WAIT(1); \
        __syncthreads(); \
        if (i + 2 < nchunk) \
            gemm_load_stage(Ahi, Alo, Bhi, Blo, K, m0, n0, (i + 2) * BK, \
                            smem_base + ((i + 2) % NSTAGE) * STAGE_B, tid); \
        CP_COMMIT(); \
        const uint32_t st = smem_base + (i % NSTAGE) * STAGE_B; \
        const uint32_t sAhi = st + 0 * TILE_B, sAlo = st + 1 * TILE_B; \
        const uint32_t sBhi = st + 2 * TILE_B, sBlo = st + 3 * TILE_B; \
        _Pragma("unroll") \
        for (int s = 0; s < 2; s++) { \
            uint32_t bh[4][2], bl[4][2]; \
            _Pragma("unroll") \
            for (int p = 0; p < 2; p++) { \
                uint32_t r0, r1, r2, r3; \
                ldsm_x4(sBhi + swz64(b_row_in_tile + p * 16, 2 * s + b_g), r0, r1, r2, r3); \
                bh[2 * p][0] = r0; bh[2 * p][1] = r1; bh[2 * p + 1][0] = r2; bh[2 * p + 1][1] = r3; \
                ldsm_x4(sBlo + swz64(b_row_in_tile + p * 16, 2 * s + b_g), r0, r1, r2, r3); \
                bl[2 * p][0] = r0; bl[2 * p][1] = r1; bl[2 * p + 1][0] = r2; bl[2 * p + 1][1] = r3; \
            } \
            _Pragma("unroll") \
            for (int mt = 0; mt < 4; mt++) { \
                uint32_t ah[4], al[4]; \
                ldsm_x4(sAhi + swz64(a_row_in_tile + mt * 16, 2 * s + a_g), \
                        ah[0], ah[1], ah[2], ah[3]); \
                ldsm_x4(sAlo + swz64(a_row_in_tile + mt * 16, 2 * s + a_g), \
                        al[0], al[1], al[2], al[3]); \
                _Pragma("unroll") \
                for (int nt = 0; nt < 4; nt++) { \
                    mma_bf16(acc[mt][nt], ah, bh[nt]); \
                    mma_bf16(acc[mt][nt], ah, bl[nt]); \
                    mma_bf16(acc[mt][nt], al, bh[nt]); \
                } \
            } \
        } \
    }

// ---------------------------------------------------------------------------
// QKV GEMM: writes head-major split q/k/v (Q pre-scaled by 1/8)
// ---------------------------------------------------------------------------
__global__ void __launch_bounds__(256, 2)
gemm_qkv(const __nv_bfloat16* __restrict__ Ahi, const __nv_bfloat16* __restrict__ Alo,
         const __nv_bfloat16* __restrict__ Bhi, const __nv_bfloat16* __restrict__ Blo,
         const float* __restrict__ bias,
         __nv_bfloat16* __restrict__ hd_hi, __nv_bfloat16* __restrict__ hd_lo)
{
    extern __shared__ __align__(128) unsigned char smem_raw[];
    const uint32_t smem_base = smem_to_u32(smem_raw);
    const int tid = threadIdx.x, wid = tid >> 5, lane = tid & 31;
    const int wm = wid >> 2, wn = wid & 3;
    const int m0 = blockIdx.y * 128, n0 = blockIdx.x * 128;
    const int K = DMODEL;

    GEMM_MAINLOOP(Ahi, Alo, Bhi, Blo, K)

    const int row_base = m0 + wm * 64 + (lane >> 2);
    const int col_base = n0 + wn * 32 + 2 * (lane & 3);
#pragma unroll
    for (int mt = 0; mt < 4; mt++) {
#pragma unroll
        for (int nt = 0; nt < 4; nt++) {
            int col = col_base + nt * 8;
            int which = col >> 10;
            int head  = (col >> 6) & 15;
            int dim   = col & 63;
            float b0 = bias[col], b1 = bias[col + 1];
            float sc = (which == 0) ? 0.125f : 1.0f;
#pragma unroll
            for (int rr = 0; rr < 2; rr++) {
                int row = row_base + mt * 16 + rr * 8;
                float v0 = (acc[mt][nt][2 * rr + 0] + b0) * sc;
                float v1 = (acc[mt][nt][2 * rr + 1] + b1) * sc;
                int bb = row >> 11, s = row & 2047;
                size_t addr = (((size_t)(which * (BATCH * NHEADS) + bb * NHEADS + head))
                               * SEQ + s) * HDIM + dim;
                uint32_t hp = pack_hi_bf16x2(v0, v1);
                __nv_bfloat162 hv = *(__nv_bfloat162*)&hp;
                float l0 = v0 - __bfloat162float(hv.x);
                float l1 = v1 - __bfloat162float(hv.y);
                *(uint32_t*)(hd_hi + addr) = hp;
                *(uint32_t*)(hd_lo + addr) = pack_hi_bf16x2(l0, l1);
            }
        }
    }
}

// ---------------------------------------------------------------------------
// Out-proj GEMM: fp32 output + bias
// ---------------------------------------------------------------------------
__global__ void __launch_bounds__(256, 2)
gemm_splitbf16(const __nv_bfloat16* __restrict__ Ahi, const __nv_bfloat16* __restrict__ Alo,
               const __nv_bfloat16* __restrict__ Bhi, const __nv_bfloat16* __restrict__ Blo,
               const float* __restrict__ bias, float* __restrict__ C,
               int M, int N, int K)
{
    extern __shared__ __align__(128) unsigned char smem_raw[];
    const uint32_t smem_base = smem_to_u32(smem_raw);
    const int tid = threadIdx.x, wid = tid >> 5, lane = tid & 31;
    const int wm = wid >> 2, wn = wid & 3;
    const int m0 = blockIdx.y * 128, n0 = blockIdx.x * 128;

    GEMM_MAINLOOP(Ahi, Alo, Bhi, Blo, K)

    const int row_base = m0 + wm * 64 + (lane >> 2);
    const int col_base = n0 + wn * 32 + 2 * (lane & 3);
#pragma unroll
    for (int mt = 0; mt < 4; mt++) {
#pragma unroll
        for (int nt = 0; nt < 4; nt++) {
            int col = col_base + nt * 8;
            float b0 = bias[col], b1 = bias[col + 1];
            int r0 = row_base + mt * 16;
            *(float2*)(C + (size_t)r0 * N + col) =
                make_float2(acc[mt][nt][0] + b0, acc[mt][nt][1] + b1);
            *(float2*)(C + (size_t)(r0 + 8) * N + col) =
                make_float2(acc[mt][nt][2] + b0, acc[mt][nt][3] + b1);
        }
    }
}

// ---------------------------------------------------------------------------
// Flash attention with mma.sync, split-bf16 precision.
// CTA: 64 q-rows x one (b,h), 128 threads (4 warps x 16 rows).
// 2-stage KV pipeline, 2 CTAs/SM (256 regs/thread available -> no spills).
// ---------------------------------------------------------------------------
#define ATHREADS   128
#define AT_STRIDE_B 144                    // 72 bf16 per row
#define KV_TILE_B  (64 * AT_STRIDE_B)      // 9216
#define KV_STAGE_B (4 * KV_TILE_B)         // 36864
#define Q_TILE_B   (64 * AT_STRIDE_B)      // 9216 (64 q-rows)
#define ATTN_SMEM  (2 * Q_TILE_B + 2 * KV_STAGE_B)   // 92160

__device__ __forceinline__ void attn_load_kv(
    const __nv_bfloat16* Kh, const __nv_bfloat16* Kl,
    const __nv_bfloat16* Vh, const __nv_bfloat16* Vl,
    int kc, uint32_t stg, int tid)
{
#pragma unroll
    for (int t = 0; t < 16; t++) {
        int f = tid + t * ATHREADS;        // 0..2047
        int tile = f >> 9;
        int idx  = f & 511;
        int row  = idx >> 3;
        int g    = idx & 7;
        const __nv_bfloat16* src;
        if (tile == 0)      src = Kh + (size_t)(kc + row) * HDIM + g * 8;
        else if (tile == 1) src = Kl + (size_t)(kc + row) * HDIM + g * 8;
        else if (tile == 2) src = Vh + (size_t)(kc + row) * HDIM + g * 8;
        else                src = Vl + (size_t)(kc + row) * HDIM + g * 8;
        uint32_t dst = stg + tile * KV_TILE_B + row * AT_STRIDE_B + g * 16;
        CP_ASYNC16(dst, (const void*)src);
    }
}

__global__ void __launch_bounds__(ATHREADS, 2)
attn_mma(const __nv_bfloat16* __restrict__ hd_hi, const __nv_bfloat16* __restrict__ hd_lo,
         __nv_bfloat16* __restrict__ out_hi, __nv_bfloat16* __restrict__ out_lo)
{
    extern __shared__ __align__(128) unsigned char smem_raw[];
    const uint32_t smem_base = smem_to_u32(smem_raw);
    const int tid  = threadIdx.x;
    const int w    = tid >> 5;             // 0..3
    const int lane = tid & 31;
    const int bh   = blockIdx.y;
    const int q0   = (gridDim.x - 1 - blockIdx.x) * 64;   // longest CTAs first
    const int b    = bh >> 4;
    const int h    = bh & 15;

    const size_t headelems = (size_t)SEQ * HDIM;
    const __nv_bfloat16* Qh = hd_hi + (size_t)bh * headelems;
    const __nv_bfloat16* Ql = hd_lo + (size_t)bh * headelems;
    const __nv_bfloat16* Kh = hd_hi + (size_t)(BATCH * NHEADS + bh) * headelems;
    const __nv_bfloat16* Kl = hd_lo + (size_t)(BATCH * NHEADS + bh) * headelems;
    const __nv_bfloat16* Vh = hd_hi + (size_t)(2 * BATCH * NHEADS + bh) * headelems;
    const __nv_bfloat16* Vl = hd_lo + (size_t)(2 * BATCH * NHEADS + bh) * headelems;

    const uint32_t sQh = smem_base;
    const uint32_t sQl = smem_base + Q_TILE_B;
    const uint32_t kvbase = smem_base + 2 * Q_TILE_B;

    // ---- Prologue: Q tile (64 rows, hi+lo) + KV chunks 0 and 1 ----
#pragma unroll
    for (int t = 0; t < 8; t++) {
        int f = tid + t * ATHREADS;        // 0..1023
        int half = f >> 9;
        int idx  = f & 511;
        int row  = idx >> 3;
        int g    = idx & 7;
        const __nv_bfloat16* src = (half ? Ql : Qh) + (size_t)(q0 + row) * HDIM + g * 8;
        uint32_t dst = (half ? sQl : sQh) + row * AT_STRIDE_B + g * 16;
        CP_ASYNC16(dst, (const void*)src);
    }
    attn_load_kv(Kh, Kl, Vh, Vl, 0, kvbase, tid);
    CP_COMMIT();
    attn_load_kv(Kh, Kl, Vh, Vl, 64, kvbase + KV_STAGE_B, tid);
    CP_COMMIT();

    const int nch = q0 / 64 + 1;

    // per-thread state (fully resident: 2 CTAs/SM allows 256 regs/thread)
    uint32_t qh[4][4], ql[4][4];
    float o[8][4];
#pragma unroll
    for (int j = 0; j < 8; j++)
#pragma unroll
        for (int e = 0; e < 4; e++) o[j][e] = 0.f;
    float m0r = -1e30f, m1r = -1e30f, l0r = 0.f, l1r = 0.f;
    bool qloaded = false;

    const int g0 = q0 + 16 * w + (lane >> 2);
    const int g1 = g0 + 8;
    const int cb = 2 * (lane & 3);
    const int krow  = ((lane >> 4) * 8) + (lane & 7);
    const int kcolb = ((lane >> 3) & 1) * 16;
    const uint32_t qrow_off = (16 * w + (lane & 15)) * AT_STRIDE_B + (lane >> 4) * 16;

    for (int c = 0; c < nch; c++) {
        CP_WAIT(1);
        __syncthreads();

        if (!qloaded) {
            qloaded = true;
#pragma unroll
            for (int s = 0; s < 4; s++) {
                ldsm_x4(sQh + qrow_off + s * 32, qh[s][0], qh[s][1], qh[s][2], qh[s][3]);
                ldsm_x4(sQl + qrow_off + s * 32, ql[s][0], ql[s][1], ql[s][2], ql[s][3]);
            }
        }

        const int kc = c * 64;
        const bool active = (kc <= q0 + 16 * w + 15);
        if (active) {
            const uint32_t stg = kvbase + (c & 1) * KV_STAGE_B;
            const uint32_t sKh = stg, sKl = stg + KV_TILE_B;
            const uint32_t sVh = stg + 2 * KV_TILE_B, sVl = stg + 3 * KV_TILE_B;

            // ---- S = Q K^T (3-pass split) ----
            float sfr[8][4];
#pragma unroll
            for (int j = 0; j < 8; j++)
#pragma unroll
                for (int e = 0; e < 4; e++) sfr[j][e] = 0.f;

#pragma unroll
            for (int s = 0; s < 4; s++) {
#pragma unroll
                for (int p = 0; p < 4; p++) {
                    uint32_t h0, h1, h2, h3, lo0, lo1, lo2, lo3;
                    ldsm_x4(sKh + (16 * p + krow) * AT_STRIDE_B + s * 32 + kcolb, h0, h1, h2, h3);
                    ldsm_x4(sKl + (16 * p + krow) * AT_STRIDE_B + s * 32 + kcolb, lo0, lo1, lo2, lo3);
                    uint32_t bh0[2] = {h0, h1}, bh1[2] = {h2, h3};
                    uint32_t bl0[2] = {lo0, lo1}, bl1[2] = {lo2, lo3};
                    mma_bf16(sfr[2 * p],     qh[s], bh0);
                    mma_bf16(sfr[2 * p],     qh[s], bl0);
                    mma_bf16(sfr[2 * p],     ql[s], bh0);
                    mma_bf16(sfr[2 * p + 1], qh[s], bh1);
                    mma_bf16(sfr[2 * p + 1], qh[s], bl1);
                    mma_bf16(sfr[2 * p + 1], ql[s], bh1);
                }
            }

            // ---- causal mask ----
            if (kc + 63 > g0) {
#pragma unroll
                for (int j = 0; j < 8; j++) {
                    int col = kc + 8 * j + cb;
                    if (col     > g0) sfr[j][0] = -1e30f;
                    if (col + 1 > g0) sfr[j][1] = -1e30f;
                    if (col     > g1) sfr[j][2] = -1e30f;
                    if (col + 1 > g1) sfr[j][3] = -1e30f;
                }
            }

            // ---- online softmax (exp in place) ----
            float mx0 = -1e30f, mx1 = -1e30f;
#pragma unroll
            for (int j = 0; j < 8; j++) {
                mx0 = fmaxf(mx0, fmaxf(sfr[j][0], sfr[j][1]));
                mx1 = fmaxf(mx1, fmaxf(sfr[j][2], sfr[j][3]));
            }
            mx0 = fmaxf(mx0, __shfl_xor_sync(0xffffffffu, mx0, 1));
            mx0 = fmaxf(mx0, __shfl_xor_sync(0xffffffffu, mx0, 2));
            mx1 = fmaxf(mx1, __shfl_xor_sync(0xffffffffu, mx1, 1));
            mx1 = fmaxf(mx1, __shfl_xor_sync(0xffffffffu, mx1, 2));

            float mn0 = fmaxf(m0r, mx0), mn1 = fmaxf(m1r, mx1);
            float cr0 = __expf(m0r - mn0), cr1 = __expf(m1r - mn1);
            float sum0 = 0.f, sum1 = 0.f;
#pragma unroll
            for (int j = 0; j < 8; j++) {
                sfr[j][0] = __expf(sfr[j][0] - mn0);
                sfr[j][1] = __expf(sfr[j][1] - mn0);
                sfr[j][2] = __expf(sfr[j][2] - mn1);
                sfr[j][3] = __expf(sfr[j][3] - mn1);
                sum0 += sfr[j][0] + sfr[j][1];
                sum1 += sfr[j][2] + sfr[j][3];
            }
            sum0 += __shfl_xor_sync(0xffffffffu, sum0, 1);
            sum0 += __shfl_xor_sync(0xffffffffu, sum0, 2);
            sum1 += __shfl_xor_sync(0xffffffffu, sum1, 1);
            sum1 += __shfl_xor_sync(0xffffffffu, sum1, 2);

            l0r = l0r * cr0 + sum0;
            l1r = l1r * cr1 + sum1;
            m0r = mn0; m1r = mn1;
#pragma unroll
            for (int j = 0; j < 8; j++) {
                o[j][0] *= cr0; o[j][1] *= cr0;
                o[j][2] *= cr1; o[j][3] *= cr1;
            }

            // ---- O += P V (fused pack + 3-pass split) ----
#pragma unroll
            for (int t = 0; t < 4; t++) {
                uint32_t ph[4], pl[4];
                {
                    const float* s0p = sfr[2 * t];
                    const float* s1p = sfr[2 * t + 1];
                    float v[8] = {s0p[0], s0p[1], s0p[2], s0p[3],
                                  s1p[0], s1p[1], s1p[2], s1p[3]};
#pragma unroll
                    for (int q = 0; q < 4; q++) {
                        uint32_t hp = pack_hi_bf16x2(v[2 * q], v[2 * q + 1]);
                        __nv_bfloat162 hv = *(__nv_bfloat162*)&hp;
                        float lo0 = v[2 * q]     - __bfloat162float(hv.x);
                        float lo1 = v[2 * q + 1] - __bfloat162float(hv.y);
                        ph[q] = hp;
                        pl[q] = pack_hi_bf16x2(lo0, lo1);
                    }
                }
#pragma unroll
                for (int d = 0; d < 4; d++) {
                    uint32_t v0, v1, v2, v3, w0, w1, w2, w3;
                    uint32_t a = sVh + (16 * t + (lane & 15)) * AT_STRIDE_B + d * 32 + (lane >> 4) * 16;
                    ldsm_x4_t(a, v0, v1, v2, v3);
                    a = sVl + (16 * t + (lane & 15)) * AT_STRIDE_B + d * 32 + (lane >> 4) * 16;
                    ldsm_x4_t(a, w0, w1, w2, w3);
                    uint32_t bh0[2] = {v0, v1}, bh1[2] = {v2, v3};
                    uint32_t bl0[2] = {w0, w1}, bl1[2] = {w2, w3};
                    mma_bf16(o[2 * d],     ph, bh0);
                    mma_bf16(o[2 * d],     ph, bl0);
                    mma_bf16(o[2 * d],     pl, bh0);
                    mma_bf16(o[2 * d + 1], ph, bh1);
                    mma_bf16(o[2 * d + 1], ph, bl1);
                    mma_bf16(o[2 * d + 1], pl, bh1);
                }
            }
        }
        __syncthreads();   // all warps done reading stage c&1
        if (c + 2 < nch)
            attn_load_kv(Kh, Kl, Vh, Vl, (c + 2) * 64,
                         kvbase + (c & 1) * KV_STAGE_B, tid);
        CP_COMMIT();
    }
    CP_WAIT(0);   // drain speculative prologue prefetch before exit

    // ---- epilogue: normalize, split, store ----
    const float i0 = 1.0f / l0r, i1 = 1.0f / l1r;
    const size_t base0 = ((size_t)(b * SEQ + g0)) * DMODEL + h * HDIM + cb;
    const size_t base1 = ((size_t)(b * SEQ + g1)) * DMODEL + h * HDIM + cb;
#pragma unroll
    for (int j = 0; j < 8; j++) {
        float x0 = o[j][0] * i0, x1 = o[j][1] * i0;
        float y0 = o[j][2] * i1, y1 = o[j][3] * i1;
        uint32_t hp0 = pack_hi_bf16x2(x0, x1);
        __nv_bfloat162 hv0 = *(__nv_bfloat162*)&hp0;
        uint32_t lp0 = pack_hi_bf16x2(x0 - __bfloat162float(hv0.x),
                                      x1 - __bfloat162float(hv0.y));
        uint32_t hp1 = pack_hi_bf16x2(y0, y1);
        __nv_bfloat162 hv1 = *(__nv_bfloat162*)&hp1;
        uint32_t lp1 = pack_hi_bf16x2(y0 - __bfloat162float(hv1.x),
                                      y1 - __bfloat162float(hv1.y));
        *(uint32_t*)(out_hi + base0 + 8 * j) = hp0;
        *(uint32_t*)(out_lo + base0 + 8 * j) = lp0;
        *(uint32_t*)(out_hi + base1 + 8 * j) = hp1;
        *(uint32_t*)(out_lo + base1 + 8 * j) = lp1;
    }
}

// ---------------------------------------------------------------------------
// Launch
// ---------------------------------------------------------------------------
extern "C" void kernel_launch(void* const* d_in, const int* in_sizes, int n_in,
                              void* d_out, int out_size)
{
    const float* x     = (const float*)d_in[0];
    const float* w_qkv = (const float*)d_in[1];
    const float* b_qkv = (const float*)d_in[2];
    const float* w_out = (const float*)d_in[3];
    const float* b_out = (const float*)d_in[4];
    float* out = (float*)d_out;

    __nv_bfloat16 *x_hi, *x_lo, *wq_hi, *wq_lo, *wo_hi, *wo_lo;
    __nv_bfloat16 *hd_hi, *hd_lo, *at_hi, *at_lo;
    cudaGetSymbolAddress((void**)&x_hi,  g_x_hi);
    cudaGetSymbolAddress((void**)&x_lo,  g_x_lo);
    cudaGetSymbolAddress((void**)&wq_hi, g_wqkv_hi);
    cudaGetSymbolAddress((void**)&wq_lo, g_wqkv_lo);
    cudaGetSymbolAddress((void**)&wo_hi, g_wout_hi);
    cudaGetSymbolAddress((void**)&wo_lo, g_wout_lo);
    cudaGetSymbolAddress((void**)&hd_hi, g_hd_hi);
    cudaGetSymbolAddress((void**)&hd_lo, g_hd_lo);
    cudaGetSymbolAddress((void**)&at_hi, g_attn_hi);
    cudaGetSymbolAddress((void**)&at_lo, g_attn_lo);

    cudaFuncSetAttribute(gemm_qkv,
                         cudaFuncAttributeMaxDynamicSharedMemorySize, GEMM_SMEM);
    cudaFuncSetAttribute(gemm_splitbf16,
                         cudaFuncAttributeMaxDynamicSharedMemorySize, GEMM_SMEM);
    cudaFuncSetAttribute(attn_mma,
                         cudaFuncAttributeMaxDynamicSharedMemorySize, ATTN_SMEM);

    // Unified splits (1 launch)
    {
        int total = NX4 + NQ4 + NO4;
        split_all_kernel<<<(total + 255) / 256, 256>>>(
            x, w_qkv, w_out, x_hi, x_lo, wq_hi, wq_lo, wo_hi, wo_lo);
    }

    // 1) QKV projection -> head-major split q/k/v
    {
        dim3 grid(QKVDIM / 128, TOKENS / 128);
        gemm_qkv<<<grid, 256, GEMM_SMEM>>>(x_hi, x_lo, wq_hi, wq_lo, b_qkv, hd_hi, hd_lo);
    }

    // 2) Flash attention (64-row CTAs, 2 CTAs/SM) -> split attn output
    {
        dim3 grid(SEQ / 64, BATCH * NHEADS);
        attn_mma<<<grid, ATHREADS, ATTN_SMEM>>>(hd_hi, hd_lo, at_hi, at_lo);
    }

    // 3) Output projection
    {
        dim3 grid(DMODEL / 128, TOKENS / 128);
        gemm_splitbf16<<<grid, 256, GEMM_SMEM>>>(
            at_hi, at_lo, wo_hi, wo_lo, b_out, out, TOKENS, DMODEL, DMODEL);
    }
}